// round 14
// baseline (speedup 1.0000x reference)
#include <cuda_runtime.h>
#include <cuda_fp16.h>
#include <cstdint>

// Problem constants
#define B_   4
#define L_   2048
#define E_   1024
#define H_   16
#define D_   64
#define MTOK (B_*L_)
#define SCALE   0.125f

// ---------------------------------------------------------------------------
// Static device scratch (all-fp16 operand pipeline)
// ---------------------------------------------------------------------------
__device__ __half g_Qh[(size_t)MTOK * E_], g_Ql[(size_t)MTOK * E_]; // Q fp16 hi/lo
__device__ __half g_K[(size_t)MTOK * E_];                           // K plain fp16
__device__ __half g_Vh[(size_t)MTOK * E_], g_Vl[(size_t)MTOK * E_]; // V fp16 hi/lo
__device__ __half g_Xq[(size_t)MTOK * E_];                          // inputs, plain fp16
__device__ __half g_Xk[(size_t)MTOK * E_];
__device__ __half g_Xv[(size_t)MTOK * E_];
__device__ __half g_Wqh[(size_t)E_ * E_], g_Wql[(size_t)E_ * E_];   // weights fp16 hi/lo
__device__ __half g_Wkh[(size_t)E_ * E_], g_Wkl[(size_t)E_ * E_];
__device__ __half g_Wvh[(size_t)E_ * E_], g_Wvl[(size_t)E_ * E_];
__device__ __half g_Woh[(size_t)E_ * E_], g_Wol[(size_t)E_ * E_];
__device__ __half g_C[(size_t)MTOK * E_];                           // ctx, plain fp16
__device__ uint32_t g_mbits[(size_t)B_ * L_ * (L_ / 32)];           // 2 MB bitmask
__device__ float g_sl[(size_t)B_ * H_ * L_];                        // row sum of exp
__device__ __half g_eatt[(size_t)B_ * H_ * L_ * L_];                // fp16 exp scratch
__device__ float g_att_fallback[(size_t)B_ * H_ * L_ * L_];

// ---------------------------------------------------------------------------
// PTX helpers
// ---------------------------------------------------------------------------
__device__ __forceinline__ uint32_t smem_u32(const void* p) {
    uint32_t a;
    asm("{ .reg .u64 t; cvta.to.shared.u64 t, %1; cvt.u32.u64 %0, t; }"
        : "=r"(a) : "l"(p));
    return a;
}
__device__ __forceinline__ void cp16(uint32_t dst, const void* src) {
    asm volatile("cp.async.cg.shared.global [%0], [%1], 16;" :: "r"(dst), "l"(src));
}
#define CP_COMMIT() asm volatile("cp.async.commit_group;" ::: "memory")
#define CP_WAIT(n)  asm volatile("cp.async.wait_group %0;" :: "n"(n) : "memory")

__device__ __forceinline__ void ldsm4(uint32_t* r, uint32_t a) {
    asm volatile("ldmatrix.sync.aligned.m8n8.x4.shared.b16 {%0,%1,%2,%3}, [%4];"
                 : "=r"(r[0]), "=r"(r[1]), "=r"(r[2]), "=r"(r[3]) : "r"(a));
}
__device__ __forceinline__ void ldsm4t(uint32_t* r, uint32_t a) {
    asm volatile("ldmatrix.sync.aligned.m8n8.x4.trans.shared.b16 {%0,%1,%2,%3}, [%4];"
                 : "=r"(r[0]), "=r"(r[1]), "=r"(r[2]), "=r"(r[3]) : "r"(a));
}
// fp16 MMA
__device__ __forceinline__ void mma16816h(float* c, const uint32_t* a, const uint32_t* b) {
    asm volatile("mma.sync.aligned.m16n8k16.row.col.f32.f16.f16.f32 "
                 "{%0,%1,%2,%3}, {%4,%5,%6,%7}, {%8,%9}, {%0,%1,%2,%3};"
                 : "+f"(c[0]), "+f"(c[1]), "+f"(c[2]), "+f"(c[3])
                 : "r"(a[0]), "r"(a[1]), "r"(a[2]), "r"(a[3]), "r"(b[0]), "r"(b[1]));
}

__device__ __forceinline__ uint32_t swz(int row, int colb) {
    uint32_t off = ((uint32_t)row << 7) + (uint32_t)colb;
    return off ^ (((uint32_t)row & 7u) << 4);
}
__device__ __forceinline__ uint32_t pack_hf2(__half a, __half b) {
    return (uint32_t)__half_as_ushort(b) << 16 | (uint32_t)__half_as_ushort(a);
}

// ---------------------------------------------------------------------------
// cp.async tile loader (16-bit element tiles, 128B rows)
// ---------------------------------------------------------------------------
template<int ROWS, typename T>
__device__ __forceinline__ void cpa_tile(uint32_t dst, const T* __restrict__ src,
                                         int stride, int tid)
{
#pragma unroll
    for (int t = 0; t < ROWS * 8 / 256; t++) {
        int idx = tid + t * 256;
        int r = idx >> 3, u = idx & 7;
        cp16(dst + swz(r, u * 16), src + (size_t)r * stride + u * 8);
    }
}

// ---------------------------------------------------------------------------
// Fused prologue: 3 input fp16 converts + 4 weight hi/lo converts + mask bits
// ---------------------------------------------------------------------------
__device__ __forceinline__ void conv_h(const float* __restrict__ src,
                                       __half* __restrict__ d, int i)
{
    float4 v = ((const float4*)src)[i];
    uint2 p;
    p.x = pack_hf2(__float2half(v.x), __float2half(v.y));
    p.y = pack_hf2(__float2half(v.z), __float2half(v.w));
    ((uint2*)d)[i] = p;
}
__device__ __forceinline__ void conv_hl(const float* __restrict__ src,
                                        __half* __restrict__ h,
                                        __half* __restrict__ l, int i)
{
    float4 v = ((const float4*)src)[i];
    __half h0 = __float2half(v.x), h1 = __float2half(v.y);
    __half h2 = __float2half(v.z), h3 = __float2half(v.w);
    __half l0 = __float2half(v.x - __half2float(h0));
    __half l1 = __float2half(v.y - __half2float(h1));
    __half l2 = __float2half(v.z - __half2float(h2));
    __half l3 = __float2half(v.w - __half2float(h3));
    uint2 hp; hp.x = pack_hf2(h0, h1); hp.y = pack_hf2(h2, h3);
    uint2 lp; lp.x = pack_hf2(l0, l1); lp.y = pack_hf2(l2, l3);
    ((uint2*)h)[i] = hp;
    ((uint2*)l)[i] = lp;
}

__global__ __launch_bounds__(256)
void prep_all(const float* iq, const float* ik, const float* iv, const int* mask,
              const float* wq, const float* wk, const float* wv, const float* wo,
              __half* xq, __half* xk, __half* xv,
              __half* wqh, __half* wql, __half* wkh, __half* wkl,
              __half* wvh, __half* wvl, __half* woh, __half* wol,
              uint32_t* bits)
{
    const int bx = blockIdx.x;
    const int tid = threadIdx.x;
    if (bx < 24576) {                       // X converts: 3 x 8192 blocks
        int z = bx >> 13, blk = bx & 8191;
        const float* s = (z == 0) ? iq : (z == 1) ? ik : iv;
        __half* d = (z == 0) ? xq : (z == 1) ? xk : xv;
        conv_h(s, d, blk * 256 + tid);
    } else if (bx < 24576 + 4096) {         // W converts: 4 x 1024 blocks
        int t = bx - 24576;
        int z = t >> 10, blk = t & 1023;
        const float* s = (z == 0) ? wq : (z == 1) ? wk : (z == 2) ? wv : wo;
        __half* h = (z == 0) ? wqh : (z == 1) ? wkh : (z == 2) ? wvh : woh;
        __half* l = (z == 0) ? wql : (z == 1) ? wkl : (z == 2) ? wvl : wol;
        conv_hl(s, h, l, blk * 256 + tid);
    } else {                                // mask bitfield
        int blk = bx - 28672;
        int warp = tid >> 5, lane = tid & 31;
        int base = blk * 1024 + warp * 128;
#pragma unroll
        for (int r = 0; r < 4; r++) {
            int idx = base + r * 32 + lane;
            uint32_t bal = __ballot_sync(0xffffffffu, mask[idx] != 0);
            if (lane == 0) bits[idx >> 5] = bal;
        }
    }
}

// ---------------------------------------------------------------------------
// MMA chunk cores (warp tile 32x32, MF=2, NF=4, 64-wide K chunk)
// ---------------------------------------------------------------------------
#define MF 2
#define NF 4

// fp16 2-product (proj + AV): A single fp16 tile, B fp16 hi/lo, trans B
__device__ __forceinline__ void chunk_h2(float (*acc)[NF][4],
                                         uint32_t uA, uint32_t uBh, uint32_t uBl,
                                         int mw, int nw, int lane)
{
#pragma unroll
    for (int ks = 0; ks < 4; ks++) {
        uint32_t a[MF][4], b_h[NF][2], b_l[NF][2];
        int acol = ks * 32 + ((lane >> 4) << 4);
#pragma unroll
        for (int mf = 0; mf < MF; mf++)
            ldsm4(a[mf], uA + swz(mw + mf * 16 + (lane & 15), acol));
#pragma unroll
        for (int np = 0; np < NF / 2; np++) {
            uint32_t r4[4];
            uint32_t sw = swz(ks * 16 + (lane & 15),
                              (nw + np * 16) * 2 + ((lane >> 4) << 4));
            ldsm4t(r4, uBh + sw);
            b_h[np*2][0] = r4[0]; b_h[np*2][1] = r4[1];
            b_h[np*2+1][0] = r4[2]; b_h[np*2+1][1] = r4[3];
            ldsm4t(r4, uBl + sw);
            b_l[np*2][0] = r4[0]; b_l[np*2][1] = r4[1];
            b_l[np*2+1][0] = r4[2]; b_l[np*2+1][1] = r4[3];
        }
#pragma unroll
        for (int mf = 0; mf < MF; mf++)
#pragma unroll
            for (int nf = 0; nf < NF; nf++) {
                mma16816h(acc[mf][nf], a[mf], b_h[nf]);
                mma16816h(acc[mf][nf], a[mf], b_l[nf]);
            }
    }
}

// scores: A = Q fp16 hi/lo, B = K plain fp16 (n-major, non-trans); 2 products
__device__ __forceinline__ void chunk_sc(float (*acc)[NF][4],
                                         uint32_t uAh, uint32_t uAl, uint32_t uB,
                                         int mw, int nw, int lane)
{
#pragma unroll
    for (int ks = 0; ks < 4; ks++) {
        uint32_t a_h[MF][4], a_l[MF][4], b[NF][2];
        int acol = ks * 32 + ((lane >> 4) << 4);
#pragma unroll
        for (int mf = 0; mf < MF; mf++) {
            uint32_t sw = swz(mw + mf * 16 + (lane & 15), acol);
            ldsm4(a_h[mf], uAh + sw);
            ldsm4(a_l[mf], uAl + sw);
        }
#pragma unroll
        for (int np = 0; np < NF / 2; np++) {
            uint32_t r4[4];
            uint32_t sw = swz(nw + np * 16 + ((lane >> 4) << 3) + (lane & 7),
                              ks * 32 + ((lane & 8) << 1));
            ldsm4(r4, uB + sw);
            b[np*2][0] = r4[0]; b[np*2][1] = r4[1];
            b[np*2+1][0] = r4[2]; b[np*2+1][1] = r4[3];
        }
#pragma unroll
        for (int mf = 0; mf < MF; mf++)
#pragma unroll
            for (int nf = 0; nf < NF; nf++) {
                mma16816h(acc[mf][nf], a_h[mf], b[nf]);
                mma16816h(acc[mf][nf], a_l[mf], b[nf]);
            }
    }
}

// ---------------------------------------------------------------------------
// Projection GEMM body (block 128m x 64n, 16 chunks, single sync/chunk)
// OUT: 0 = fp32 row-major, 2 = fp16 hi/lo split-head, 3 = plain fp16 split-head
// ---------------------------------------------------------------------------
#define PROJ_SMEM (2 * 32768)

template<int OUT>
__device__ __forceinline__ void proj_body(
    const __half* __restrict__ Xa,
    const __half* __restrict__ Wh, const __half* __restrict__ Wl,
    const float* __restrict__ bias,
    float* __restrict__ out, __half* __restrict__ Oh, __half* __restrict__ Ol,
    char* sm, int n0, int m0)
{
    const uint32_t sb = smem_u32(sm);
    const int tid = threadIdx.x;
    const int wid = tid >> 5, lane = tid & 31;
    const int mw = (wid >> 1) * 32;
    const int nw = (wid & 1) * 32;

    float acc[MF][NF][4];
#pragma unroll
    for (int i = 0; i < MF; i++)
#pragma unroll
        for (int j = 0; j < NF; j++)
#pragma unroll
            for (int kk = 0; kk < 4; kk++) acc[i][j][kk] = 0.0f;

    const __half* Asrc = Xa + (size_t)m0 * E_;

    cpa_tile<128>(sb,         Asrc, E_, tid);
    cpa_tile<64>(sb + 16384,  Wh + n0, E_, tid);
    cpa_tile<64>(sb + 24576,  Wl + n0, E_, tid);
    CP_COMMIT();

    for (int c = 0; c < 16; c++) {
        const uint32_t bc = sb + (c & 1) * 32768;
        CP_WAIT(0);
        __syncthreads();
        if (c < 15) {   // issue-after-sync
            const uint32_t bn = sb + ((c + 1) & 1) * 32768;
            int k1 = (c + 1) * 64;
            cpa_tile<128>(bn,         Asrc + k1, E_, tid);
            cpa_tile<64>(bn + 16384,  Wh + (size_t)k1 * E_ + n0, E_, tid);
            cpa_tile<64>(bn + 24576,  Wl + (size_t)k1 * E_ + n0, E_, tid);
            CP_COMMIT();
        }
        chunk_h2(acc, bc, bc + 16384, bc + 24576, mw, nw, lane);
    }

    const int g = lane >> 2, tg = lane & 3;
#pragma unroll
    for (int mf = 0; mf < MF; mf++)
#pragma unroll
        for (int nf = 0; nf < NF; nf++) {
            int row = m0 + mw + mf * 16 + g;
            int col = n0 + nw + nf * 8 + tg * 2;
            float b0 = bias[col], b1 = bias[col + 1];
            float x0 = acc[mf][nf][0] + b0, y0 = acc[mf][nf][1] + b1;
            float x1 = acc[mf][nf][2] + b0, y1 = acc[mf][nf][3] + b1;
            if (OUT == 0) {
                float* dst = out + (size_t)row * E_ + col;
                *(float2*)dst            = make_float2(x0, y0);
                *(float2*)(dst + 8 * E_) = make_float2(x1, y1);
            } else {
                int b = row >> 11, l = row & (L_ - 1);
                int h = col >> 6, d = col & (D_ - 1);
                size_t i0 = (((size_t)(b * H_ + h)) * L_ + l) * D_ + d;
                size_t i1 = i0 + 8 * D_;
                __half hx0 = __float2half(x0), hy0 = __float2half(y0);
                __half hx1 = __float2half(x1), hy1 = __float2half(y1);
                *(uint32_t*)&Oh[i0] = pack_hf2(hx0, hy0);
                *(uint32_t*)&Oh[i1] = pack_hf2(hx1, hy1);
                if (OUT == 2) {
                    __half lx0 = __float2half(x0 - __half2float(hx0));
                    __half ly0 = __float2half(y0 - __half2float(hy0));
                    __half lx1 = __float2half(x1 - __half2float(hx1));
                    __half ly1 = __float2half(y1 - __half2float(hy1));
                    *(uint32_t*)&Ol[i0] = pack_hf2(lx0, ly0);
                    *(uint32_t*)&Ol[i1] = pack_hf2(lx1, ly1);
                }
            }
        }
}

// QKV fused: z selects projection
__global__ __launch_bounds__(256, 2)
void proj_qkv(const __half* Xq, const __half* Xk, const __half* Xv,
              const __half* Wqh, const __half* Wql, const __half* Wkh, const __half* Wkl,
              const __half* Wvh, const __half* Wvl,
              const float* bq, const float* bk, const float* bv,
              __half* Qh, __half* Ql, __half* Kp, __half* Vh, __half* Vl)
{
    extern __shared__ char sm[];
    int z = blockIdx.z;
    if (z == 0) {
        proj_body<2>(Xq, Wqh, Wql, bq, nullptr, Qh, Ql,
                     sm, blockIdx.x * 64, blockIdx.y * 128);
    } else if (z == 1) {
        proj_body<3>(Xk, Wkh, Wkl, bk, nullptr, Kp, nullptr,
                     sm, blockIdx.x * 64, blockIdx.y * 128);
    } else {
        proj_body<2>(Xv, Wvh, Wvl, bv, nullptr, Vh, Vl,
                     sm, blockIdx.x * 64, blockIdx.y * 128);
    }
}

__global__ __launch_bounds__(256, 2)
void proj_o(const __half* C, const __half* Wh, const __half* Wl,
            const float* bo, float* out)
{
    extern __shared__ char sm[];
    proj_body<0>(C, Wh, Wl, bo, out, nullptr, nullptr,
                 sm, blockIdx.x * 64, blockIdx.y * 128);
}

// ---------------------------------------------------------------------------
// Kernel: scores (fp16 2-product) -> eatt fp16 (masked -> 0); row sums -> gl.
// bh = blockIdx.y + bh0 (quarter offset for stream pipelining)
// smem (dynamic, 80KB): Qh 16K | Ql 16K | K 2x8K | mask bits 32K @49152
// ---------------------------------------------------------------------------
#define SCORES_SMEM (81920)

__global__ __launch_bounds__(256, 2)
void scores_mma(const __half* __restrict__ Qh, const __half* __restrict__ Ql,
                const __half* __restrict__ Kp,
                const uint32_t* __restrict__ mbits, __half* __restrict__ eatt,
                float* __restrict__ gl, int bh0)
{
    extern __shared__ char sm[];
    __shared__ float sRed[128][2];
    const uint32_t sb = smem_u32(sm);
    const uint32_t* sBits = (const uint32_t*)(sm + 49152);   // [128][64]
    const int tid = threadIdx.x;
    const int wid = tid >> 5, lane = tid & 31;
    const int mw = (wid >> 1) * 32;
    const int nw = (wid & 1) * 32;
    const int q0 = blockIdx.x * 128;
    const int bh = blockIdx.y + bh0;
    const int b  = bh >> 4;
    const int g = lane >> 2, tg = lane & 3;

    const __half* Kb = Kp + (size_t)bh * L_ * D_;
    const uint32_t* bb = mbits + ((size_t)b * L_ + q0) * (L_ / 32);
    __half* eb = eatt + (size_t)bh * L_ * L_;

    cpa_tile<128>(sb,         Qh + ((size_t)bh * L_ + q0) * D_, D_, tid);
    cpa_tile<128>(sb + 16384, Ql + ((size_t)bh * L_ + q0) * D_, D_, tid);
#pragma unroll
    for (int t = 0; t < 8; t++) {
        int idx = tid + t * 256;
        cp16(sb + 49152 + idx * 16, bb + idx * 4);
    }
    cpa_tile<64>(sb + 32768,  Kb, D_, tid);
    CP_COMMIT();

    float rs[MF][2];
#pragma unroll
    for (int i = 0; i < MF; i++) rs[i][0] = rs[i][1] = 0.0f;

    for (int kt = 0; kt < 32; kt++) {
        const uint32_t kb = sb + 32768 + (kt & 1) * 8192;
        CP_WAIT(0);
        __syncthreads();
        if (kt < 31) {   // issue-after-sync
            const uint32_t kn = sb + 32768 + ((kt + 1) & 1) * 8192;
            cpa_tile<64>(kn, Kb + (size_t)(kt + 1) * 64 * D_, D_, tid);
            CP_COMMIT();
        }

        float acc[MF][NF][4];
#pragma unroll
        for (int i = 0; i < MF; i++)
#pragma unroll
            for (int j = 0; j < NF; j++)
#pragma unroll
                for (int kk = 0; kk < 4; kk++) acc[i][j][kk] = 0.0f;

        chunk_sc(acc, sb, sb + 16384, kb, mw, nw, lane);

        const int k0 = kt * 64;
#pragma unroll
        for (int mf = 0; mf < MF; mf++) {
            const int r0 = mw + mf * 16 + g;
            const int r1 = r0 + 8;
#pragma unroll
            for (int nf = 0; nf < NF; nf++) {
                int knw = nw + nf * 8 + tg * 2;
                int wsel = kt * 2 + (knw >> 5);
                uint32_t w0 = sBits[r0 * 64 + wsel];
                uint32_t w1 = sBits[r1 * 64 + wsel];
                int bp = knw & 31;
                float2 e1, e2;
                e1.x = (w0 >> bp) & 1u       ? __expf(acc[mf][nf][0] * SCALE) : 0.0f;
                e1.y = (w0 >> (bp + 1)) & 1u ? __expf(acc[mf][nf][1] * SCALE) : 0.0f;
                e2.x = (w1 >> bp) & 1u       ? __expf(acc[mf][nf][2] * SCALE) : 0.0f;
                e2.y = (w1 >> (bp + 1)) & 1u ? __expf(acc[mf][nf][3] * SCALE) : 0.0f;
                rs[mf][0] += e1.x + e1.y;
                rs[mf][1] += e2.x + e2.y;
                *(__half2*)(eb + (size_t)(q0 + r0) * L_ + k0 + knw) =
                    __floats2half2_rn(e1.x, e1.y);
                *(__half2*)(eb + (size_t)(q0 + r1) * L_ + k0 + knw) =
                    __floats2half2_rn(e2.x, e2.y);
            }
        }
    }

#pragma unroll
    for (int mf = 0; mf < MF; mf++)
#pragma unroll
        for (int rr = 0; rr < 2; rr++) {
            float s = rs[mf][rr];
            s += __shfl_xor_sync(0xffffffffu, s, 1);
            s += __shfl_xor_sync(0xffffffffu, s, 2);
            if (tg == 0) sRed[mw + mf * 16 + g + rr * 8][wid & 1] = s;
        }
    __syncthreads();
    if (tid < 128)
        gl[(size_t)bh * L_ + q0 + tid] = sRed[tid][0] + sRed[tid][1];
}

// ---------------------------------------------------------------------------
// Kernel: AV (fp16 MMA) + normalization.  bh = blockIdx.y + bh0.
// smem (dynamic, 64KB): At 16K | V 3 x 16K (depth-3 pipeline)
// ---------------------------------------------------------------------------
#define AV_SMEM (65536)

__global__ __launch_bounds__(256, 2)
void av_mma(const __half* __restrict__ eatt, float* __restrict__ att,
            const __half* __restrict__ Vh, const __half* __restrict__ Vl,
            const float* __restrict__ gl, __half* __restrict__ C, int bh0)
{
    extern __shared__ char sm[];
    char* At = sm;
    __shared__ float sI[128];
    const uint32_t sb = smem_u32(sm);
    const int tid = threadIdx.x;
    const int wid = tid >> 5, lane = tid & 31;
    const int mw = (wid >> 1) * 32;
    const int nw = (wid & 1) * 32;
    const int m0 = blockIdx.x * 128;
    const int bh = blockIdx.y + bh0;
    const int b  = bh >> 4, h = bh & 15;

    const __half* Eb = eatt + (size_t)bh * L_ * L_ + (size_t)m0 * L_;
    float*        Ao = att  + (size_t)bh * L_ * L_ + (size_t)m0 * L_;
    const __half* Vbh = Vh + (size_t)bh * L_ * D_;
    const __half* Vbl = Vl + (size_t)bh * L_ * D_;

    if (tid < 128) sI[tid] = 1.0f / gl[(size_t)bh * L_ + m0 + tid];

    float acc[MF][NF][4];
#pragma unroll
    for (int i = 0; i < MF; i++)
#pragma unroll
        for (int j = 0; j < NF; j++)
#pragma unroll
            for (int kk = 0; kk < 4; kk++) acc[i][j][kk] = 0.0f;

    uint2 ea[8];
#pragma unroll
    for (int t = 0; t < 8; t++) {
        int idx = tid + t * 256;
        int r = idx >> 4, q = idx & 15;
        ea[t] = *(const uint2*)(Eb + (size_t)r * L_ + q * 4);
    }
    cpa_tile<64>(sb + 16384, Vbh, D_, tid);
    cpa_tile<64>(sb + 24576, Vbl, D_, tid);
    CP_COMMIT();
    cpa_tile<64>(sb + 32768, Vbh + (size_t)64 * D_, D_, tid);
    cpa_tile<64>(sb + 40960, Vbl + (size_t)64 * D_, D_, tid);
    CP_COMMIT();
    __syncthreads();    // sI visible

#pragma unroll
    for (int t = 0; t < 8; t++) {
        int idx = tid + t * 256;
        int r = idx >> 4, q = idx & 15;
        float2 f01 = __half22float2(*(__half2*)&ea[t].x);
        float2 f23 = __half22float2(*(__half2*)&ea[t].y);
        float4 p;
        p.x = f01.x * sI[r]; p.y = f01.y * sI[r];
        p.z = f23.x * sI[r]; p.w = f23.y * sI[r];
        *(float4*)(Ao + (size_t)r * L_ + q * 4) = p;
        *(uint2*)(At + swz(r, q * 8)) = ea[t];
    }

    for (int c = 0; c < 32; c++) {
        const uint32_t vb = sb + 16384 + (c % 3) * 16384;
        if (c < 31) {
#pragma unroll
            for (int t = 0; t < 8; t++) {
                int idx = tid + t * 256;
                int r = idx >> 4, q = idx & 15;
                ea[t] = *(const uint2*)(Eb + (size_t)r * L_ + (c + 1) * 64 + q * 4);
            }
        }
        if (c + 2 < 32) {
            const uint32_t vn = sb + 16384 + ((c + 2) % 3) * 16384;
            cpa_tile<64>(vn,        Vbh + (size_t)(c + 2) * 64 * D_, D_, tid);
            cpa_tile<64>(vn + 8192, Vbl + (size_t)(c + 2) * 64 * D_, D_, tid);
            CP_COMMIT();
            CP_WAIT(2);
        } else {
            CP_WAIT(0);
        }
        __syncthreads();
        chunk_h2(acc, sb, vb, vb + 8192, mw, nw, lane);
        __syncthreads();
        if (c < 31) {
#pragma unroll
            for (int t = 0; t < 8; t++) {
                int idx = tid + t * 256;
                int r = idx >> 4, q = idx & 15;
                float2 f01 = __half22float2(*(__half2*)&ea[t].x);
                float2 f23 = __half22float2(*(__half2*)&ea[t].y);
                float4 p;
                p.x = f01.x * sI[r]; p.y = f01.y * sI[r];
                p.z = f23.x * sI[r]; p.w = f23.y * sI[r];
                *(float4*)(Ao + (size_t)r * L_ + (c + 1) * 64 + q * 4) = p;
                *(uint2*)(At + swz(r, q * 8)) = ea[t];
            }
        }
    }

    // epilogue: scale unnormalized ctx rows by inv_l, write plain fp16
    const int g = lane >> 2, tg = lane & 3;
#pragma unroll
    for (int mf = 0; mf < MF; mf++)
#pragma unroll
        for (int nf = 0; nf < NF; nf++) {
            int r0l = mw + mf * 16 + g;
            int r1l = r0l + 8;
            float s0 = sI[r0l], s1 = sI[r1l];
            int m   = m0 + r0l;
            int col = nw + nf * 8 + tg * 2;
            size_t i0 = ((size_t)b * L_ + m) * E_ + h * D_ + col;
            size_t i1 = i0 + 8 * E_;
            *(uint32_t*)&C[i0] = pack_hf2(__float2half(acc[mf][nf][0] * s0),
                                          __float2half(acc[mf][nf][1] * s0));
            *(uint32_t*)&C[i1] = pack_hf2(__float2half(acc[mf][nf][2] * s1),
                                          __float2half(acc[mf][nf][3] * s1));
        }
}

// ---------------------------------------------------------------------------
// Launch: forked-stream pipeline  (scores quarter i -> av quarter i overlap)
// ---------------------------------------------------------------------------
extern "C" void kernel_launch(void* const* d_in, const int* in_sizes, int n_in,
                              void* d_out, int out_size)
{
    const float* iq = (const float*)d_in[0];
    const float* ik = (const float*)d_in[1];
    const float* iv = (const float*)d_in[2];
    const int*   mk = (const int*)  d_in[3];
    const float* Wq = (const float*)d_in[4];
    const float* bq = (const float*)d_in[5];
    const float* Wk = (const float*)d_in[6];
    const float* bk = (const float*)d_in[7];
    const float* Wv = (const float*)d_in[8];
    const float* bv = (const float*)d_in[9];
    const float* Wo = (const float*)d_in[10];
    const float* bo = (const float*)d_in[11];

    float* o_out = (float*)d_out;
    const long long o_elems   = (long long)MTOK * E_;
    const long long att_elems = (long long)B_ * H_ * L_ * L_;

    __half *Qh, *Ql, *Kp, *Vh, *Vl, *Ea, *Cc, *Xq, *Xk, *Xv;
    __half *Wqh, *Wql, *Wkh, *Wkl, *Wvh, *Wvl, *Woh, *Wol;
    uint32_t* Mb;
    float *Slv, *Ap;
    cudaGetSymbolAddress((void**)&Qh, g_Qh);   cudaGetSymbolAddress((void**)&Ql, g_Ql);
    cudaGetSymbolAddress((void**)&Kp, g_K);
    cudaGetSymbolAddress((void**)&Vh, g_Vh);   cudaGetSymbolAddress((void**)&Vl, g_Vl);
    cudaGetSymbolAddress((void**)&Xq, g_Xq);
    cudaGetSymbolAddress((void**)&Xk, g_Xk);
    cudaGetSymbolAddress((void**)&Xv, g_Xv);
    cudaGetSymbolAddress((void**)&Wqh, g_Wqh); cudaGetSymbolAddress((void**)&Wql, g_Wql);
    cudaGetSymbolAddress((void**)&Wkh, g_Wkh); cudaGetSymbolAddress((void**)&Wkl, g_Wkl);
    cudaGetSymbolAddress((void**)&Wvh, g_Wvh); cudaGetSymbolAddress((void**)&Wvl, g_Wvl);
    cudaGetSymbolAddress((void**)&Woh, g_Woh); cudaGetSymbolAddress((void**)&Wol, g_Wol);
    cudaGetSymbolAddress((void**)&Cc, g_C);
    cudaGetSymbolAddress((void**)&Mb, g_mbits);
    cudaGetSymbolAddress((void**)&Slv, g_sl);
    cudaGetSymbolAddress((void**)&Ea, g_eatt);
    cudaGetSymbolAddress((void**)&Ap, g_att_fallback);

    float* att = ((long long)out_size >= o_elems + att_elems)
                     ? (o_out + o_elems) : Ap;

    cudaFuncSetAttribute(proj_qkv,   cudaFuncAttributeMaxDynamicSharedMemorySize, PROJ_SMEM);
    cudaFuncSetAttribute(proj_o,     cudaFuncAttributeMaxDynamicSharedMemorySize, PROJ_SMEM);
    cudaFuncSetAttribute(scores_mma, cudaFuncAttributeMaxDynamicSharedMemorySize, SCORES_SMEM);
    cudaFuncSetAttribute(av_mma,     cudaFuncAttributeMaxDynamicSharedMemorySize, AV_SMEM);

    // fork a second stream for the av pipeline (capture-safe fork-join)
    cudaStream_t sB;
    cudaStreamCreateWithFlags(&sB, cudaStreamNonBlocking);
    cudaEvent_t eQ, eS0, eS1, eS2, eS3, eJ;
    cudaEventCreateWithFlags(&eQ,  cudaEventDisableTiming);
    cudaEventCreateWithFlags(&eS0, cudaEventDisableTiming);
    cudaEventCreateWithFlags(&eS1, cudaEventDisableTiming);
    cudaEventCreateWithFlags(&eS2, cudaEventDisableTiming);
    cudaEventCreateWithFlags(&eS3, cudaEventDisableTiming);
    cudaEventCreateWithFlags(&eJ,  cudaEventDisableTiming);
    cudaEvent_t eS[4] = {eS0, eS1, eS2, eS3};

    // prologue + QKV projection on origin stream
    prep_all<<<45056, 256>>>(iq, ik, iv, mk, Wq, Wk, Wv, Wo,
                             Xq, Xk, Xv,
                             Wqh, Wql, Wkh, Wkl, Wvh, Wvl, Woh, Wol, Mb);
    dim3 gp(E_ / 64, MTOK / 128, 3);
    proj_qkv<<<gp, 256, PROJ_SMEM>>>(Xq, Xk, Xv,
                                     Wqh, Wql, Wkh, Wkl, Wvh, Wvl,
                                     bq, bk, bv, Qh, Ql, Kp, Vh, Vl);
    cudaEventRecord(eQ, 0);
    cudaStreamWaitEvent(sB, eQ, 0);

    // pipelined scores (origin stream) / av (stream B) per bh quarter
    dim3 gq(L_ / 128, 16);                      // (16, 16) per quarter
    for (int q = 0; q < 4; q++) {
        scores_mma<<<gq, 256, SCORES_SMEM>>>(Qh, Ql, Kp, Mb, Ea, Slv, q * 16);
        cudaEventRecord(eS[q], 0);
        cudaStreamWaitEvent(sB, eS[q], 0);
        av_mma<<<gq, 256, AV_SMEM, sB>>>(Ea, att, Vh, Vl, Slv, Cc, q * 16);
    }

    // join and output projection on origin stream
    cudaEventRecord(eJ, sB);
    cudaStreamWaitEvent(0, eJ, 0);
    dim3 go(E_ / 64, MTOK / 128);
    proj_o<<<go, 256, PROJ_SMEM>>>(Cc, Woh, Wol, bo, o_out);
}

// round 15
// speedup vs baseline: 1.0564x; 1.0564x over previous
#include <cuda_runtime.h>
#include <cuda_fp16.h>
#include <cstdint>

// Problem constants
#define B_   4
#define L_   2048
#define E_   1024
#define H_   16
#define D_   64
#define MTOK (B_*L_)
#define SCALE   0.125f

// ---------------------------------------------------------------------------
// Static device scratch (all-fp16 operand pipeline)
// ---------------------------------------------------------------------------
__device__ __half g_Qh[(size_t)MTOK * E_], g_Ql[(size_t)MTOK * E_]; // Q fp16 hi/lo
__device__ __half g_K[(size_t)MTOK * E_];                           // K plain fp16
__device__ __half g_Vh[(size_t)MTOK * E_], g_Vl[(size_t)MTOK * E_]; // V fp16 hi/lo
__device__ __half g_Xq[(size_t)MTOK * E_];                          // inputs, plain fp16
__device__ __half g_Xk[(size_t)MTOK * E_];
__device__ __half g_Xv[(size_t)MTOK * E_];
__device__ __half g_Wqh[(size_t)E_ * E_], g_Wql[(size_t)E_ * E_];   // weights fp16 hi/lo
__device__ __half g_Wkh[(size_t)E_ * E_], g_Wkl[(size_t)E_ * E_];
__device__ __half g_Wvh[(size_t)E_ * E_], g_Wvl[(size_t)E_ * E_];
__device__ __half g_Woh[(size_t)E_ * E_], g_Wol[(size_t)E_ * E_];
__device__ __half g_C[(size_t)MTOK * E_];                           // ctx, plain fp16
__device__ uint32_t g_mbits[(size_t)B_ * L_ * (L_ / 32)];           // 2 MB bitmask
__device__ float g_sl[(size_t)B_ * H_ * L_];                        // row sum of exp
__device__ __half g_eatt[(size_t)B_ * H_ * L_ * L_];                // fp16 exp scratch
__device__ float g_att_fallback[(size_t)B_ * H_ * L_ * L_];

// ---------------------------------------------------------------------------
// PTX helpers
// ---------------------------------------------------------------------------
__device__ __forceinline__ uint32_t smem_u32(const void* p) {
    uint32_t a;
    asm("{ .reg .u64 t; cvta.to.shared.u64 t, %1; cvt.u32.u64 %0, t; }"
        : "=r"(a) : "l"(p));
    return a;
}
__device__ __forceinline__ void cp16(uint32_t dst, const void* src) {
    asm volatile("cp.async.cg.shared.global [%0], [%1], 16;" :: "r"(dst), "l"(src));
}
#define CP_COMMIT() asm volatile("cp.async.commit_group;" ::: "memory")
#define CP_WAIT(n)  asm volatile("cp.async.wait_group %0;" :: "n"(n) : "memory")

__device__ __forceinline__ void ldsm4(uint32_t* r, uint32_t a) {
    asm volatile("ldmatrix.sync.aligned.m8n8.x4.shared.b16 {%0,%1,%2,%3}, [%4];"
                 : "=r"(r[0]), "=r"(r[1]), "=r"(r[2]), "=r"(r[3]) : "r"(a));
}
__device__ __forceinline__ void ldsm4t(uint32_t* r, uint32_t a) {
    asm volatile("ldmatrix.sync.aligned.m8n8.x4.trans.shared.b16 {%0,%1,%2,%3}, [%4];"
                 : "=r"(r[0]), "=r"(r[1]), "=r"(r[2]), "=r"(r[3]) : "r"(a));
}
// fp16 MMA
__device__ __forceinline__ void mma16816h(float* c, const uint32_t* a, const uint32_t* b) {
    asm volatile("mma.sync.aligned.m16n8k16.row.col.f32.f16.f16.f32 "
                 "{%0,%1,%2,%3}, {%4,%5,%6,%7}, {%8,%9}, {%0,%1,%2,%3};"
                 : "+f"(c[0]), "+f"(c[1]), "+f"(c[2]), "+f"(c[3])
                 : "r"(a[0]), "r"(a[1]), "r"(a[2]), "r"(a[3]), "r"(b[0]), "r"(b[1]));
}

__device__ __forceinline__ uint32_t swz(int row, int colb) {
    uint32_t off = ((uint32_t)row << 7) + (uint32_t)colb;
    return off ^ (((uint32_t)row & 7u) << 4);
}
__device__ __forceinline__ uint32_t pack_hf2(__half a, __half b) {
    return (uint32_t)__half_as_ushort(b) << 16 | (uint32_t)__half_as_ushort(a);
}

// ---------------------------------------------------------------------------
// cp.async tile loader (16-bit element tiles, 128B rows)
// ---------------------------------------------------------------------------
template<int ROWS, typename T>
__device__ __forceinline__ void cpa_tile(uint32_t dst, const T* __restrict__ src,
                                         int stride, int tid)
{
#pragma unroll
    for (int t = 0; t < ROWS * 8 / 256; t++) {
        int idx = tid + t * 256;
        int r = idx >> 3, u = idx & 7;
        cp16(dst + swz(r, u * 16), src + (size_t)r * stride + u * 8);
    }
}

// ---------------------------------------------------------------------------
// Fused prologue: 3 input fp16 converts + 4 weight hi/lo converts + mask bits
// ---------------------------------------------------------------------------
__device__ __forceinline__ void conv_h(const float* __restrict__ src,
                                       __half* __restrict__ d, int i)
{
    float4 v = ((const float4*)src)[i];
    uint2 p;
    p.x = pack_hf2(__float2half(v.x), __float2half(v.y));
    p.y = pack_hf2(__float2half(v.z), __float2half(v.w));
    ((uint2*)d)[i] = p;
}
__device__ __forceinline__ void conv_hl(const float* __restrict__ src,
                                        __half* __restrict__ h,
                                        __half* __restrict__ l, int i)
{
    float4 v = ((const float4*)src)[i];
    __half h0 = __float2half(v.x), h1 = __float2half(v.y);
    __half h2 = __float2half(v.z), h3 = __float2half(v.w);
    __half l0 = __float2half(v.x - __half2float(h0));
    __half l1 = __float2half(v.y - __half2float(h1));
    __half l2 = __float2half(v.z - __half2float(h2));
    __half l3 = __float2half(v.w - __half2float(h3));
    uint2 hp; hp.x = pack_hf2(h0, h1); hp.y = pack_hf2(h2, h3);
    uint2 lp; lp.x = pack_hf2(l0, l1); lp.y = pack_hf2(l2, l3);
    ((uint2*)h)[i] = hp;
    ((uint2*)l)[i] = lp;
}

__global__ __launch_bounds__(256)
void prep_all(const float* iq, const float* ik, const float* iv, const int* mask,
              const float* wq, const float* wk, const float* wv, const float* wo,
              __half* xq, __half* xk, __half* xv,
              __half* wqh, __half* wql, __half* wkh, __half* wkl,
              __half* wvh, __half* wvl, __half* woh, __half* wol,
              uint32_t* bits)
{
    const int bx = blockIdx.x;
    const int tid = threadIdx.x;
    if (bx < 24576) {                       // X converts: 3 x 8192 blocks
        int z = bx >> 13, blk = bx & 8191;
        const float* s = (z == 0) ? iq : (z == 1) ? ik : iv;
        __half* d = (z == 0) ? xq : (z == 1) ? xk : xv;
        conv_h(s, d, blk * 256 + tid);
    } else if (bx < 24576 + 4096) {         // W converts: 4 x 1024 blocks
        int t = bx - 24576;
        int z = t >> 10, blk = t & 1023;
        const float* s = (z == 0) ? wq : (z == 1) ? wk : (z == 2) ? wv : wo;
        __half* h = (z == 0) ? wqh : (z == 1) ? wkh : (z == 2) ? wvh : woh;
        __half* l = (z == 0) ? wql : (z == 1) ? wkl : (z == 2) ? wvl : wol;
        conv_hl(s, h, l, blk * 256 + tid);
    } else {                                // mask bitfield
        int blk = bx - 28672;
        int warp = tid >> 5, lane = tid & 31;
        int base = blk * 1024 + warp * 128;
#pragma unroll
        for (int r = 0; r < 4; r++) {
            int idx = base + r * 32 + lane;
            uint32_t bal = __ballot_sync(0xffffffffu, mask[idx] != 0);
            if (lane == 0) bits[idx >> 5] = bal;
        }
    }
}

// ---------------------------------------------------------------------------
// MMA chunk cores (warp tile 32x32, MF=2, NF=4, 64-wide K chunk)
// ---------------------------------------------------------------------------
#define MF 2
#define NF 4

// fp16 2-product (proj + AV): A single fp16 tile, B fp16 hi/lo, trans B
__device__ __forceinline__ void chunk_h2(float (*acc)[NF][4],
                                         uint32_t uA, uint32_t uBh, uint32_t uBl,
                                         int mw, int nw, int lane)
{
#pragma unroll
    for (int ks = 0; ks < 4; ks++) {
        uint32_t a[MF][4], b_h[NF][2], b_l[NF][2];
        int acol = ks * 32 + ((lane >> 4) << 4);
#pragma unroll
        for (int mf = 0; mf < MF; mf++)
            ldsm4(a[mf], uA + swz(mw + mf * 16 + (lane & 15), acol));
#pragma unroll
        for (int np = 0; np < NF / 2; np++) {
            uint32_t r4[4];
            uint32_t sw = swz(ks * 16 + (lane & 15),
                              (nw + np * 16) * 2 + ((lane >> 4) << 4));
            ldsm4t(r4, uBh + sw);
            b_h[np*2][0] = r4[0]; b_h[np*2][1] = r4[1];
            b_h[np*2+1][0] = r4[2]; b_h[np*2+1][1] = r4[3];
            ldsm4t(r4, uBl + sw);
            b_l[np*2][0] = r4[0]; b_l[np*2][1] = r4[1];
            b_l[np*2+1][0] = r4[2]; b_l[np*2+1][1] = r4[3];
        }
#pragma unroll
        for (int mf = 0; mf < MF; mf++)
#pragma unroll
            for (int nf = 0; nf < NF; nf++) {
                mma16816h(acc[mf][nf], a[mf], b_h[nf]);
                mma16816h(acc[mf][nf], a[mf], b_l[nf]);
            }
    }
}

// scores: A = Q fp16 hi/lo, B = K plain fp16 (n-major, non-trans); 2 products
__device__ __forceinline__ void chunk_sc(float (*acc)[NF][4],
                                         uint32_t uAh, uint32_t uAl, uint32_t uB,
                                         int mw, int nw, int lane)
{
#pragma unroll
    for (int ks = 0; ks < 4; ks++) {
        uint32_t a_h[MF][4], a_l[MF][4], b[NF][2];
        int acol = ks * 32 + ((lane >> 4) << 4);
#pragma unroll
        for (int mf = 0; mf < MF; mf++) {
            uint32_t sw = swz(mw + mf * 16 + (lane & 15), acol);
            ldsm4(a_h[mf], uAh + sw);
            ldsm4(a_l[mf], uAl + sw);
        }
#pragma unroll
        for (int np = 0; np < NF / 2; np++) {
            uint32_t r4[4];
            uint32_t sw = swz(nw + np * 16 + ((lane >> 4) << 3) + (lane & 7),
                              ks * 32 + ((lane & 8) << 1));
            ldsm4(r4, uB + sw);
            b[np*2][0] = r4[0]; b[np*2][1] = r4[1];
            b[np*2+1][0] = r4[2]; b[np*2+1][1] = r4[3];
        }
#pragma unroll
        for (int mf = 0; mf < MF; mf++)
#pragma unroll
            for (int nf = 0; nf < NF; nf++) {
                mma16816h(acc[mf][nf], a_h[mf], b[nf]);
                mma16816h(acc[mf][nf], a_l[mf], b[nf]);
            }
    }
}

// ---------------------------------------------------------------------------
// Projection GEMM body (block 128m x 64n, 16 chunks, single sync/chunk)
// OUT: 0 = fp32 row-major, 2 = fp16 hi/lo split-head, 3 = plain fp16 split-head
// ---------------------------------------------------------------------------
#define PROJ_SMEM (2 * 32768)

template<int OUT>
__device__ __forceinline__ void proj_body(
    const __half* __restrict__ Xa,
    const __half* __restrict__ Wh, const __half* __restrict__ Wl,
    const float* __restrict__ bias,
    float* __restrict__ out, __half* __restrict__ Oh, __half* __restrict__ Ol,
    char* sm, int n0, int m0)
{
    const uint32_t sb = smem_u32(sm);
    const int tid = threadIdx.x;
    const int wid = tid >> 5, lane = tid & 31;
    const int mw = (wid >> 1) * 32;
    const int nw = (wid & 1) * 32;

    float acc[MF][NF][4];
#pragma unroll
    for (int i = 0; i < MF; i++)
#pragma unroll
        for (int j = 0; j < NF; j++)
#pragma unroll
            for (int kk = 0; kk < 4; kk++) acc[i][j][kk] = 0.0f;

    const __half* Asrc = Xa + (size_t)m0 * E_;

    cpa_tile<128>(sb,         Asrc, E_, tid);
    cpa_tile<64>(sb + 16384,  Wh + n0, E_, tid);
    cpa_tile<64>(sb + 24576,  Wl + n0, E_, tid);
    CP_COMMIT();

    for (int c = 0; c < 16; c++) {
        const uint32_t bc = sb + (c & 1) * 32768;
        CP_WAIT(0);
        __syncthreads();
        if (c < 15) {   // issue-after-sync
            const uint32_t bn = sb + ((c + 1) & 1) * 32768;
            int k1 = (c + 1) * 64;
            cpa_tile<128>(bn,         Asrc + k1, E_, tid);
            cpa_tile<64>(bn + 16384,  Wh + (size_t)k1 * E_ + n0, E_, tid);
            cpa_tile<64>(bn + 24576,  Wl + (size_t)k1 * E_ + n0, E_, tid);
            CP_COMMIT();
        }
        chunk_h2(acc, bc, bc + 16384, bc + 24576, mw, nw, lane);
    }

    const int g = lane >> 2, tg = lane & 3;
#pragma unroll
    for (int mf = 0; mf < MF; mf++)
#pragma unroll
        for (int nf = 0; nf < NF; nf++) {
            int row = m0 + mw + mf * 16 + g;
            int col = n0 + nw + nf * 8 + tg * 2;
            float b0 = bias[col], b1 = bias[col + 1];
            float x0 = acc[mf][nf][0] + b0, y0 = acc[mf][nf][1] + b1;
            float x1 = acc[mf][nf][2] + b0, y1 = acc[mf][nf][3] + b1;
            if (OUT == 0) {
                float* dst = out + (size_t)row * E_ + col;
                *(float2*)dst            = make_float2(x0, y0);
                *(float2*)(dst + 8 * E_) = make_float2(x1, y1);
            } else {
                int b = row >> 11, l = row & (L_ - 1);
                int h = col >> 6, d = col & (D_ - 1);
                size_t i0 = (((size_t)(b * H_ + h)) * L_ + l) * D_ + d;
                size_t i1 = i0 + 8 * D_;
                __half hx0 = __float2half(x0), hy0 = __float2half(y0);
                __half hx1 = __float2half(x1), hy1 = __float2half(y1);
                *(uint32_t*)&Oh[i0] = pack_hf2(hx0, hy0);
                *(uint32_t*)&Oh[i1] = pack_hf2(hx1, hy1);
                if (OUT == 2) {
                    __half lx0 = __float2half(x0 - __half2float(hx0));
                    __half ly0 = __float2half(y0 - __half2float(hy0));
                    __half lx1 = __float2half(x1 - __half2float(hx1));
                    __half ly1 = __float2half(y1 - __half2float(hy1));
                    *(uint32_t*)&Ol[i0] = pack_hf2(lx0, ly0);
                    *(uint32_t*)&Ol[i1] = pack_hf2(lx1, ly1);
                }
            }
        }
}

// QKV fused: z selects projection
__global__ __launch_bounds__(256, 2)
void proj_qkv(const __half* Xq, const __half* Xk, const __half* Xv,
              const __half* Wqh, const __half* Wql, const __half* Wkh, const __half* Wkl,
              const __half* Wvh, const __half* Wvl,
              const float* bq, const float* bk, const float* bv,
              __half* Qh, __half* Ql, __half* Kp, __half* Vh, __half* Vl)
{
    extern __shared__ char sm[];
    int z = blockIdx.z;
    if (z == 0) {
        proj_body<2>(Xq, Wqh, Wql, bq, nullptr, Qh, Ql,
                     sm, blockIdx.x * 64, blockIdx.y * 128);
    } else if (z == 1) {
        proj_body<3>(Xk, Wkh, Wkl, bk, nullptr, Kp, nullptr,
                     sm, blockIdx.x * 64, blockIdx.y * 128);
    } else {
        proj_body<2>(Xv, Wvh, Wvl, bv, nullptr, Vh, Vl,
                     sm, blockIdx.x * 64, blockIdx.y * 128);
    }
}

__global__ __launch_bounds__(256, 2)
void proj_o(const __half* C, const __half* Wh, const __half* Wl,
            const float* bo, float* out)
{
    extern __shared__ char sm[];
    proj_body<0>(C, Wh, Wl, bo, out, nullptr, nullptr,
                 sm, blockIdx.x * 64, blockIdx.y * 128);
}

// ---------------------------------------------------------------------------
// Kernel: scores (fp16 2-product) -> eatt fp16 (masked -> 0); row sums -> gl.
// smem (dynamic, 96KB): Qh 16K | Ql 16K | K 4x8K @32768 | mask bits 32K @65536
// K pipeline depth 4; single sync per chunk.
// ---------------------------------------------------------------------------
#define SCORES_SMEM (98304)

__global__ __launch_bounds__(256, 2)
void scores_mma(const __half* __restrict__ Qh, const __half* __restrict__ Ql,
                const __half* __restrict__ Kp,
                const uint32_t* __restrict__ mbits, __half* __restrict__ eatt,
                float* __restrict__ gl)
{
    extern __shared__ char sm[];
    __shared__ float sRed[128][2];
    const uint32_t sb = smem_u32(sm);
    const uint32_t* sBits = (const uint32_t*)(sm + 65536);   // [128][64]
    const int tid = threadIdx.x;
    const int wid = tid >> 5, lane = tid & 31;
    const int mw = (wid >> 1) * 32;
    const int nw = (wid & 1) * 32;
    const int q0 = blockIdx.x * 128;
    const int bh = blockIdx.y;
    const int b  = bh >> 4;
    const int g = lane >> 2, tg = lane & 3;

    const __half* Kb = Kp + (size_t)bh * L_ * D_;
    const uint32_t* bb = mbits + ((size_t)b * L_ + q0) * (L_ / 32);
    __half* eb = eatt + (size_t)bh * L_ * L_;

    // prologue: Q + bits + K0 (group 0), K1 (group 1), K2 (group 2)
    cpa_tile<128>(sb,         Qh + ((size_t)bh * L_ + q0) * D_, D_, tid);
    cpa_tile<128>(sb + 16384, Ql + ((size_t)bh * L_ + q0) * D_, D_, tid);
#pragma unroll
    for (int t = 0; t < 8; t++) {
        int idx = tid + t * 256;
        cp16(sb + 65536 + idx * 16, bb + idx * 4);
    }
    cpa_tile<64>(sb + 32768, Kb, D_, tid);
    CP_COMMIT();
    cpa_tile<64>(sb + 32768 + 8192, Kb + (size_t)64 * D_, D_, tid);
    CP_COMMIT();
    cpa_tile<64>(sb + 32768 + 16384, Kb + (size_t)128 * D_, D_, tid);
    CP_COMMIT();

    float rs[MF][2];
#pragma unroll
    for (int i = 0; i < MF; i++) rs[i][0] = rs[i][1] = 0.0f;

    for (int kt = 0; kt < 32; kt++) {
        const uint32_t kb = sb + 32768 + (kt & 3) * 8192;
        if (kt < 30)      CP_WAIT(2);
        else if (kt == 30) CP_WAIT(1);
        else               CP_WAIT(0);
        __syncthreads();
        if (kt + 3 < 32) {   // issue-after-sync (buffer (kt+3)&3 free: mma kt-1 done)
            cpa_tile<64>(sb + 32768 + ((kt + 3) & 3) * 8192,
                         Kb + (size_t)(kt + 3) * 64 * D_, D_, tid);
            CP_COMMIT();
        }

        float acc[MF][NF][4];
#pragma unroll
        for (int i = 0; i < MF; i++)
#pragma unroll
            for (int j = 0; j < NF; j++)
#pragma unroll
                for (int kk = 0; kk < 4; kk++) acc[i][j][kk] = 0.0f;

        chunk_sc(acc, sb, sb + 16384, kb, mw, nw, lane);

        const int k0 = kt * 64;
#pragma unroll
        for (int mf = 0; mf < MF; mf++) {
            const int r0 = mw + mf * 16 + g;
            const int r1 = r0 + 8;
#pragma unroll
            for (int nf = 0; nf < NF; nf++) {
                int knw = nw + nf * 8 + tg * 2;
                int wsel = kt * 2 + (knw >> 5);
                uint32_t w0 = sBits[r0 * 64 + wsel];
                uint32_t w1 = sBits[r1 * 64 + wsel];
                int bp = knw & 31;
                float2 e1, e2;
                e1.x = (w0 >> bp) & 1u       ? __expf(acc[mf][nf][0] * SCALE) : 0.0f;
                e1.y = (w0 >> (bp + 1)) & 1u ? __expf(acc[mf][nf][1] * SCALE) : 0.0f;
                e2.x = (w1 >> bp) & 1u       ? __expf(acc[mf][nf][2] * SCALE) : 0.0f;
                e2.y = (w1 >> (bp + 1)) & 1u ? __expf(acc[mf][nf][3] * SCALE) : 0.0f;
                rs[mf][0] += e1.x + e1.y;
                rs[mf][1] += e2.x + e2.y;
                *(__half2*)(eb + (size_t)(q0 + r0) * L_ + k0 + knw) =
                    __floats2half2_rn(e1.x, e1.y);
                *(__half2*)(eb + (size_t)(q0 + r1) * L_ + k0 + knw) =
                    __floats2half2_rn(e2.x, e2.y);
            }
        }
    }

#pragma unroll
    for (int mf = 0; mf < MF; mf++)
#pragma unroll
        for (int rr = 0; rr < 2; rr++) {
            float s = rs[mf][rr];
            s += __shfl_xor_sync(0xffffffffu, s, 1);
            s += __shfl_xor_sync(0xffffffffu, s, 2);
            if (tg == 0) sRed[mw + mf * 16 + g + rr * 8][wid & 1] = s;
        }
    __syncthreads();
    if (tid < 128)
        gl[(size_t)bh * L_ + q0 + tid] = sRed[tid][0] + sRed[tid][1];
}

// ---------------------------------------------------------------------------
// Kernel: AV (fp16 MMA) + normalization.  Single sync per chunk:
// At double-buffered (2x16K), V triple-buffered (3x16K).  smem = 80KB.
// ---------------------------------------------------------------------------
#define AV_SMEM (81920)

__global__ __launch_bounds__(256, 2)
void av_mma(const __half* __restrict__ eatt, float* __restrict__ att,
            const __half* __restrict__ Vh, const __half* __restrict__ Vl,
            const float* __restrict__ gl, __half* __restrict__ C)
{
    extern __shared__ char sm[];
    __shared__ float sI[128];
    const uint32_t sb = smem_u32(sm);
    const int tid = threadIdx.x;
    const int wid = tid >> 5, lane = tid & 31;
    const int mw = (wid >> 1) * 32;
    const int nw = (wid & 1) * 32;
    const int m0 = blockIdx.x * 128;
    const int bh = blockIdx.y;
    const int b  = bh >> 4, h = bh & 15;

    const __half* Eb = eatt + (size_t)bh * L_ * L_ + (size_t)m0 * L_;
    float*        Ao = att  + (size_t)bh * L_ * L_ + (size_t)m0 * L_;
    const __half* Vbh = Vh + (size_t)bh * L_ * D_;
    const __half* Vbl = Vl + (size_t)bh * L_ * D_;

    if (tid < 128) sI[tid] = 1.0f / gl[(size_t)bh * L_ + m0 + tid];

    float acc[MF][NF][4];
#pragma unroll
    for (int i = 0; i < MF; i++)
#pragma unroll
        for (int j = 0; j < NF; j++)
#pragma unroll
            for (int kk = 0; kk < 4; kk++) acc[i][j][kk] = 0.0f;

    uint2 ea[8];
    // prologue: ea(0) regs; V(0), V(1) in flight
#pragma unroll
    for (int t = 0; t < 8; t++) {
        int idx = tid + t * 256;
        int r = idx >> 4, q = idx & 15;
        ea[t] = *(const uint2*)(Eb + (size_t)r * L_ + q * 4);
    }
    cpa_tile<64>(sb + 32768, Vbh, D_, tid);
    cpa_tile<64>(sb + 40960, Vbl, D_, tid);
    CP_COMMIT();
    cpa_tile<64>(sb + 49152, Vbh + (size_t)64 * D_, D_, tid);
    cpa_tile<64>(sb + 57344, Vbl + (size_t)64 * D_, D_, tid);
    CP_COMMIT();
    __syncthreads();    // sI visible

    // chunk 0 -> At[0] (+att write); prefetch ea(1)
#pragma unroll
    for (int t = 0; t < 8; t++) {
        int idx = tid + t * 256;
        int r = idx >> 4, q = idx & 15;
        float2 f01 = __half22float2(*(__half2*)&ea[t].x);
        float2 f23 = __half22float2(*(__half2*)&ea[t].y);
        float4 p;
        p.x = f01.x * sI[r]; p.y = f01.y * sI[r];
        p.z = f23.x * sI[r]; p.w = f23.y * sI[r];
        *(float4*)(Ao + (size_t)r * L_ + q * 4) = p;
        *(uint2*)(sm + swz(r, q * 8)) = ea[t];        // At[0]
    }
#pragma unroll
    for (int t = 0; t < 8; t++) {
        int idx = tid + t * 256;
        int r = idx >> 4, q = idx & 15;
        ea[t] = *(const uint2*)(Eb + (size_t)r * L_ + 64 + q * 4);
    }

    for (int c = 0; c < 32; c++) {
        if (c < 31)      CP_WAIT(1);    // V(c) done (V(c+1) in flight)
        else             CP_WAIT(0);
        __syncthreads();                // At[c&1] visible; mma c-1 done
        if (c < 31) {
            // store ea (chunk c+1) -> At[(c+1)&1] + write normalized att
#pragma unroll
            for (int t = 0; t < 8; t++) {
                int idx = tid + t * 256;
                int r = idx >> 4, q = idx & 15;
                float2 f01 = __half22float2(*(__half2*)&ea[t].x);
                float2 f23 = __half22float2(*(__half2*)&ea[t].y);
                float4 p;
                p.x = f01.x * sI[r]; p.y = f01.y * sI[r];
                p.z = f23.x * sI[r]; p.w = f23.y * sI[r];
                *(float4*)(Ao + (size_t)r * L_ + (c + 1) * 64 + q * 4) = p;
                *(uint2*)(sm + ((c + 1) & 1) * 16384 + swz(r, q * 8)) = ea[t];
            }
            // prefetch ea(c+2) regs (rides under the mma)
            if (c < 30) {
#pragma unroll
                for (int t = 0; t < 8; t++) {
                    int idx = tid + t * 256;
                    int r = idx >> 4, q = idx & 15;
                    ea[t] = *(const uint2*)(Eb + (size_t)r * L_ + (c + 2) * 64 + q * 4);
                }
            }
            // issue V(c+2) (buffer (c+2)%3 distinct from (c)%3 and (c+1)%3)
            if (c + 2 < 32) {
                const uint32_t vn = sb + 32768 + ((c + 2) % 3) * 16384;
                cpa_tile<64>(vn,        Vbh + (size_t)(c + 2) * 64 * D_, D_, tid);
                cpa_tile<64>(vn + 8192, Vbl + (size_t)(c + 2) * 64 * D_, D_, tid);
                CP_COMMIT();
            }
        }
        const uint32_t vb = sb + 32768 + (c % 3) * 16384;
        chunk_h2(acc, sb + (c & 1) * 16384, vb, vb + 8192, mw, nw, lane);
    }

    // epilogue: scale unnormalized ctx rows by inv_l, write plain fp16
    const int g = lane >> 2, tg = lane & 3;
#pragma unroll
    for (int mf = 0; mf < MF; mf++)
#pragma unroll
        for (int nf = 0; nf < NF; nf++) {
            int r0l = mw + mf * 16 + g;
            int r1l = r0l + 8;
            float s0 = sI[r0l], s1 = sI[r1l];
            int m   = m0 + r0l;
            int col = nw + nf * 8 + tg * 2;
            size_t i0 = ((size_t)b * L_ + m) * E_ + h * D_ + col;
            size_t i1 = i0 + 8 * E_;
            *(uint32_t*)&C[i0] = pack_hf2(__float2half(acc[mf][nf][0] * s0),
                                          __float2half(acc[mf][nf][1] * s0));
            *(uint32_t*)&C[i1] = pack_hf2(__float2half(acc[mf][nf][2] * s1),
                                          __float2half(acc[mf][nf][3] * s1));
        }
}

// ---------------------------------------------------------------------------
// Launch (single stream)
// ---------------------------------------------------------------------------
extern "C" void kernel_launch(void* const* d_in, const int* in_sizes, int n_in,
                              void* d_out, int out_size)
{
    const float* iq = (const float*)d_in[0];
    const float* ik = (const float*)d_in[1];
    const float* iv = (const float*)d_in[2];
    const int*   mk = (const int*)  d_in[3];
    const float* Wq = (const float*)d_in[4];
    const float* bq = (const float*)d_in[5];
    const float* Wk = (const float*)d_in[6];
    const float* bk = (const float*)d_in[7];
    const float* Wv = (const float*)d_in[8];
    const float* bv = (const float*)d_in[9];
    const float* Wo = (const float*)d_in[10];
    const float* bo = (const float*)d_in[11];

    float* o_out = (float*)d_out;
    const long long o_elems   = (long long)MTOK * E_;
    const long long att_elems = (long long)B_ * H_ * L_ * L_;

    __half *Qh, *Ql, *Kp, *Vh, *Vl, *Ea, *Cc, *Xq, *Xk, *Xv;
    __half *Wqh, *Wql, *Wkh, *Wkl, *Wvh, *Wvl, *Woh, *Wol;
    uint32_t* Mb;
    float *Slv, *Ap;
    cudaGetSymbolAddress((void**)&Qh, g_Qh);   cudaGetSymbolAddress((void**)&Ql, g_Ql);
    cudaGetSymbolAddress((void**)&Kp, g_K);
    cudaGetSymbolAddress((void**)&Vh, g_Vh);   cudaGetSymbolAddress((void**)&Vl, g_Vl);
    cudaGetSymbolAddress((void**)&Xq, g_Xq);
    cudaGetSymbolAddress((void**)&Xk, g_Xk);
    cudaGetSymbolAddress((void**)&Xv, g_Xv);
    cudaGetSymbolAddress((void**)&Wqh, g_Wqh); cudaGetSymbolAddress((void**)&Wql, g_Wql);
    cudaGetSymbolAddress((void**)&Wkh, g_Wkh); cudaGetSymbolAddress((void**)&Wkl, g_Wkl);
    cudaGetSymbolAddress((void**)&Wvh, g_Wvh); cudaGetSymbolAddress((void**)&Wvl, g_Wvl);
    cudaGetSymbolAddress((void**)&Woh, g_Woh); cudaGetSymbolAddress((void**)&Wol, g_Wol);
    cudaGetSymbolAddress((void**)&Cc, g_C);
    cudaGetSymbolAddress((void**)&Mb, g_mbits);
    cudaGetSymbolAddress((void**)&Slv, g_sl);
    cudaGetSymbolAddress((void**)&Ea, g_eatt);
    cudaGetSymbolAddress((void**)&Ap, g_att_fallback);

    float* att = ((long long)out_size >= o_elems + att_elems)
                     ? (o_out + o_elems) : Ap;

    cudaFuncSetAttribute(proj_qkv,   cudaFuncAttributeMaxDynamicSharedMemorySize, PROJ_SMEM);
    cudaFuncSetAttribute(proj_o,     cudaFuncAttributeMaxDynamicSharedMemorySize, PROJ_SMEM);
    cudaFuncSetAttribute(scores_mma, cudaFuncAttributeMaxDynamicSharedMemorySize, SCORES_SMEM);
    cudaFuncSetAttribute(av_mma,     cudaFuncAttributeMaxDynamicSharedMemorySize, AV_SMEM);

    // fused prologue
    prep_all<<<45056, 256>>>(iq, ik, iv, mk, Wq, Wk, Wv, Wo,
                             Xq, Xk, Xv,
                             Wqh, Wql, Wkh, Wkl, Wvh, Wvl, Woh, Wol, Mb);

    // fused QKV projection
    dim3 gp(E_ / 64, MTOK / 128, 3);            // (16, 64, 3)
    proj_qkv<<<gp, 256, PROJ_SMEM>>>(Xq, Xk, Xv,
                                     Wqh, Wql, Wkh, Wkl, Wvh, Wvl,
                                     bq, bk, bv, Qh, Ql, Kp, Vh, Vl);

    // scores (depth-4 K pipeline)
    dim3 gs(L_ / 128, B_ * H_);                 // (16, 64)
    scores_mma<<<gs, 256, SCORES_SMEM>>>(Qh, Ql, Kp, Mb, Ea, Slv);

    // AV (single-sync pipeline)
    av_mma<<<gs, 256, AV_SMEM>>>(Ea, att, Vh, Vl, Slv, Cc);

    // output projection
    dim3 go(E_ / 64, MTOK / 128);               // (16, 64)
    proj_o<<<go, 256, PROJ_SMEM>>>(Cc, Woh, Wol, bo, o_out);
}

// round 16
// speedup vs baseline: 1.3108x; 1.2408x over previous
#include <cuda_runtime.h>
#include <cuda_fp16.h>
#include <cstdint>

// Problem constants
#define B_   4
#define L_   2048
#define E_   1024
#define H_   16
#define D_   64
#define MTOK (B_*L_)
#define SCALE   0.125f

// ---------------------------------------------------------------------------
// Static device scratch (pure-fp16 operand pipeline)
// ---------------------------------------------------------------------------
__device__ __half g_Q[(size_t)MTOK * E_];                           // Q fp16
__device__ __half g_K[(size_t)MTOK * E_];                           // K fp16
__device__ __half g_V[(size_t)MTOK * E_];                           // V fp16
__device__ __half g_Xq[(size_t)MTOK * E_];                          // inputs fp16
__device__ __half g_Xk[(size_t)MTOK * E_];
__device__ __half g_Xv[(size_t)MTOK * E_];
__device__ __half g_Wq[(size_t)E_ * E_], g_Wk[(size_t)E_ * E_];     // weights fp16
__device__ __half g_Wv[(size_t)E_ * E_], g_Wo[(size_t)E_ * E_];
__device__ __half g_C[(size_t)MTOK * E_];                           // ctx fp16
__device__ uint32_t g_mbits[(size_t)B_ * L_ * (L_ / 32)];           // 2 MB bitmask
__device__ float g_sl[(size_t)B_ * H_ * L_];                        // row sum of exp
__device__ __half g_eatt[(size_t)B_ * H_ * L_ * L_];                // fp16 exp scratch
__device__ float g_att_fallback[(size_t)B_ * H_ * L_ * L_];

// ---------------------------------------------------------------------------
// PTX helpers
// ---------------------------------------------------------------------------
__device__ __forceinline__ uint32_t smem_u32(const void* p) {
    uint32_t a;
    asm("{ .reg .u64 t; cvta.to.shared.u64 t, %1; cvt.u32.u64 %0, t; }"
        : "=r"(a) : "l"(p));
    return a;
}
__device__ __forceinline__ void cp16(uint32_t dst, const void* src) {
    asm volatile("cp.async.cg.shared.global [%0], [%1], 16;" :: "r"(dst), "l"(src));
}
#define CP_COMMIT() asm volatile("cp.async.commit_group;" ::: "memory")
#define CP_WAIT(n)  asm volatile("cp.async.wait_group %0;" :: "n"(n) : "memory")

__device__ __forceinline__ void ldsm4(uint32_t* r, uint32_t a) {
    asm volatile("ldmatrix.sync.aligned.m8n8.x4.shared.b16 {%0,%1,%2,%3}, [%4];"
                 : "=r"(r[0]), "=r"(r[1]), "=r"(r[2]), "=r"(r[3]) : "r"(a));
}
__device__ __forceinline__ void ldsm4t(uint32_t* r, uint32_t a) {
    asm volatile("ldmatrix.sync.aligned.m8n8.x4.trans.shared.b16 {%0,%1,%2,%3}, [%4];"
                 : "=r"(r[0]), "=r"(r[1]), "=r"(r[2]), "=r"(r[3]) : "r"(a));
}
// fp16 MMA
__device__ __forceinline__ void mma16816h(float* c, const uint32_t* a, const uint32_t* b) {
    asm volatile("mma.sync.aligned.m16n8k16.row.col.f32.f16.f16.f32 "
                 "{%0,%1,%2,%3}, {%4,%5,%6,%7}, {%8,%9}, {%0,%1,%2,%3};"
                 : "+f"(c[0]), "+f"(c[1]), "+f"(c[2]), "+f"(c[3])
                 : "r"(a[0]), "r"(a[1]), "r"(a[2]), "r"(a[3]), "r"(b[0]), "r"(b[1]));
}

__device__ __forceinline__ uint32_t swz(int row, int colb) {
    uint32_t off = ((uint32_t)row << 7) + (uint32_t)colb;
    return off ^ (((uint32_t)row & 7u) << 4);
}
__device__ __forceinline__ uint32_t pack_hf2(__half a, __half b) {
    return (uint32_t)__half_as_ushort(b) << 16 | (uint32_t)__half_as_ushort(a);
}

// ---------------------------------------------------------------------------
// cp.async tile loader (16-bit element tiles, 128B rows)
// ---------------------------------------------------------------------------
template<int ROWS, typename T>
__device__ __forceinline__ void cpa_tile(uint32_t dst, const T* __restrict__ src,
                                         int stride, int tid)
{
#pragma unroll
    for (int t = 0; t < ROWS * 8 / 256; t++) {
        int idx = tid + t * 256;
        int r = idx >> 3, u = idx & 7;
        cp16(dst + swz(r, u * 16), src + (size_t)r * stride + u * 8);
    }
}

// ---------------------------------------------------------------------------
// Fused prologue: 7 plain fp16 converts + mask bits
// ---------------------------------------------------------------------------
__device__ __forceinline__ void conv_h(const float* __restrict__ src,
                                       __half* __restrict__ d, int i)
{
    float4 v = ((const float4*)src)[i];
    uint2 p;
    p.x = pack_hf2(__float2half(v.x), __float2half(v.y));
    p.y = pack_hf2(__float2half(v.z), __float2half(v.w));
    ((uint2*)d)[i] = p;
}

__global__ __launch_bounds__(256)
void prep_all(const float* iq, const float* ik, const float* iv, const int* mask,
              const float* wq, const float* wk, const float* wv, const float* wo,
              __half* xq, __half* xk, __half* xv,
              __half* dwq, __half* dwk, __half* dwv, __half* dwo,
              uint32_t* bits)
{
    const int bx = blockIdx.x;
    const int tid = threadIdx.x;
    if (bx < 24576) {                       // X converts: 3 x 8192 blocks
        int z = bx >> 13, blk = bx & 8191;
        const float* s = (z == 0) ? iq : (z == 1) ? ik : iv;
        __half* d = (z == 0) ? xq : (z == 1) ? xk : xv;
        conv_h(s, d, blk * 256 + tid);
    } else if (bx < 24576 + 4096) {         // W converts: 4 x 1024 blocks
        int t = bx - 24576;
        int z = t >> 10, blk = t & 1023;
        const float* s = (z == 0) ? wq : (z == 1) ? wk : (z == 2) ? wv : wo;
        __half* d = (z == 0) ? dwq : (z == 1) ? dwk : (z == 2) ? dwv : dwo;
        conv_h(s, d, blk * 256 + tid);
    } else {                                // mask bitfield
        int blk = bx - 28672;
        int warp = tid >> 5, lane = tid & 31;
        int base = blk * 1024 + warp * 128;
#pragma unroll
        for (int r = 0; r < 4; r++) {
            int idx = base + r * 32 + lane;
            uint32_t bal = __ballot_sync(0xffffffffu, mask[idx] != 0);
            if (lane == 0) bits[idx >> 5] = bal;
        }
    }
}

// ---------------------------------------------------------------------------
// MMA chunk cores (warp tile 32x32, MF=2, NF=4, 64-wide K chunk, 1 product)
// ---------------------------------------------------------------------------
#define MF 2
#define NF 4

// B k-major (trans ldmatrix): proj (W rows) and av (V rows)
__device__ __forceinline__ void chunk_pt(float (*acc)[NF][4],
                                         uint32_t uA, uint32_t uB,
                                         int mw, int nw, int lane)
{
#pragma unroll
    for (int ks = 0; ks < 4; ks++) {
        uint32_t a[MF][4], b[NF][2];
        int acol = ks * 32 + ((lane >> 4) << 4);
#pragma unroll
        for (int mf = 0; mf < MF; mf++)
            ldsm4(a[mf], uA + swz(mw + mf * 16 + (lane & 15), acol));
#pragma unroll
        for (int np = 0; np < NF / 2; np++) {
            uint32_t r4[4];
            uint32_t sw = swz(ks * 16 + (lane & 15),
                              (nw + np * 16) * 2 + ((lane >> 4) << 4));
            ldsm4t(r4, uB + sw);
            b[np*2][0] = r4[0]; b[np*2][1] = r4[1];
            b[np*2+1][0] = r4[2]; b[np*2+1][1] = r4[3];
        }
#pragma unroll
        for (int mf = 0; mf < MF; mf++)
#pragma unroll
            for (int nf = 0; nf < NF; nf++)
                mma16816h(acc[mf][nf], a[mf], b[nf]);
    }
}

// B n-major (non-trans): scores (K rows = n)
__device__ __forceinline__ void chunk_sn(float (*acc)[NF][4],
                                         uint32_t uA, uint32_t uB,
                                         int mw, int nw, int lane)
{
#pragma unroll
    for (int ks = 0; ks < 4; ks++) {
        uint32_t a[MF][4], b[NF][2];
        int acol = ks * 32 + ((lane >> 4) << 4);
#pragma unroll
        for (int mf = 0; mf < MF; mf++)
            ldsm4(a[mf], uA + swz(mw + mf * 16 + (lane & 15), acol));
#pragma unroll
        for (int np = 0; np < NF / 2; np++) {
            uint32_t r4[4];
            uint32_t sw = swz(nw + np * 16 + ((lane >> 4) << 3) + (lane & 7),
                              ks * 32 + ((lane & 8) << 1));
            ldsm4(r4, uB + sw);
            b[np*2][0] = r4[0]; b[np*2][1] = r4[1];
            b[np*2+1][0] = r4[2]; b[np*2+1][1] = r4[3];
        }
#pragma unroll
        for (int mf = 0; mf < MF; mf++)
#pragma unroll
            for (int nf = 0; nf < NF; nf++)
                mma16816h(acc[mf][nf], a[mf], b[nf]);
    }
}

// ---------------------------------------------------------------------------
// Projection GEMM body (block 128m x 64n, 16 chunks, single sync/chunk)
// A plain fp16, W plain fp16, 1 MMA product.
// smem: 2 bufs x (A 16K | W 8K) = 48KB
// OUT: 0 = fp32 row-major, 3 = plain fp16 split-head
// ---------------------------------------------------------------------------
#define PROJ_SMEM (2 * 24576)

template<int OUT>
__device__ __forceinline__ void proj_body(
    const __half* __restrict__ Xa, const __half* __restrict__ W,
    const float* __restrict__ bias,
    float* __restrict__ out, __half* __restrict__ Oh,
    char* sm, int n0, int m0)
{
    const uint32_t sb = smem_u32(sm);
    const int tid = threadIdx.x;
    const int wid = tid >> 5, lane = tid & 31;
    const int mw = (wid >> 1) * 32;
    const int nw = (wid & 1) * 32;

    float acc[MF][NF][4];
#pragma unroll
    for (int i = 0; i < MF; i++)
#pragma unroll
        for (int j = 0; j < NF; j++)
#pragma unroll
            for (int kk = 0; kk < 4; kk++) acc[i][j][kk] = 0.0f;

    const __half* Asrc = Xa + (size_t)m0 * E_;

    cpa_tile<128>(sb,        Asrc, E_, tid);
    cpa_tile<64>(sb + 16384, W + n0, E_, tid);
    CP_COMMIT();

    for (int c = 0; c < 16; c++) {
        const uint32_t bc = sb + (c & 1) * 24576;
        CP_WAIT(0);
        __syncthreads();
        if (c < 15) {   // issue-after-sync
            const uint32_t bn = sb + ((c + 1) & 1) * 24576;
            int k1 = (c + 1) * 64;
            cpa_tile<128>(bn,        Asrc + k1, E_, tid);
            cpa_tile<64>(bn + 16384, W + (size_t)k1 * E_ + n0, E_, tid);
            CP_COMMIT();
        }
        chunk_pt(acc, bc, bc + 16384, mw, nw, lane);
    }

    const int g = lane >> 2, tg = lane & 3;
#pragma unroll
    for (int mf = 0; mf < MF; mf++)
#pragma unroll
        for (int nf = 0; nf < NF; nf++) {
            int row = m0 + mw + mf * 16 + g;
            int col = n0 + nw + nf * 8 + tg * 2;
            float b0 = bias[col], b1 = bias[col + 1];
            float x0 = acc[mf][nf][0] + b0, y0 = acc[mf][nf][1] + b1;
            float x1 = acc[mf][nf][2] + b0, y1 = acc[mf][nf][3] + b1;
            if (OUT == 0) {
                float* dst = out + (size_t)row * E_ + col;
                *(float2*)dst            = make_float2(x0, y0);
                *(float2*)(dst + 8 * E_) = make_float2(x1, y1);
            } else {
                int b = row >> 11, l = row & (L_ - 1);
                int h = col >> 6, d = col & (D_ - 1);
                size_t i0 = (((size_t)(b * H_ + h)) * L_ + l) * D_ + d;
                size_t i1 = i0 + 8 * D_;
                *(uint32_t*)&Oh[i0] = pack_hf2(__float2half(x0), __float2half(y0));
                *(uint32_t*)&Oh[i1] = pack_hf2(__float2half(x1), __float2half(y1));
            }
        }
}

// QKV fused: z selects projection
__global__ __launch_bounds__(256, 2)
void proj_qkv(const __half* Xq, const __half* Xk, const __half* Xv,
              const __half* Wq, const __half* Wk, const __half* Wv,
              const float* bq, const float* bk, const float* bv,
              __half* Q, __half* K, __half* V)
{
    extern __shared__ char sm[];
    int z = blockIdx.z;
    const __half* Xa = (z == 0) ? Xq : (z == 1) ? Xk : Xv;
    const __half* W  = (z == 0) ? Wq : (z == 1) ? Wk : Wv;
    const float* bias = (z == 0) ? bq : (z == 1) ? bk : bv;
    __half* O = (z == 0) ? Q : (z == 1) ? K : V;
    proj_body<3>(Xa, W, bias, nullptr, O, sm, blockIdx.x * 64, blockIdx.y * 128);
}

__global__ __launch_bounds__(256, 2)
void proj_o(const __half* C, const __half* W, const float* bo, float* out)
{
    extern __shared__ char sm[];
    proj_body<0>(C, W, bo, out, nullptr, sm, blockIdx.x * 64, blockIdx.y * 128);
}

// ---------------------------------------------------------------------------
// Kernel: scores (plain fp16, 1 product) -> eatt fp16; row sums -> gl.
// smem (dynamic, 80KB): Q 16K | K 4x8K @16384 | mask bits 32K @49152
// ---------------------------------------------------------------------------
#define SCORES_SMEM (81920)

__global__ __launch_bounds__(256, 2)
void scores_mma(const __half* __restrict__ Q, const __half* __restrict__ Kp,
                const uint32_t* __restrict__ mbits, __half* __restrict__ eatt,
                float* __restrict__ gl)
{
    extern __shared__ char sm[];
    __shared__ float sRed[128][2];
    const uint32_t sb = smem_u32(sm);
    const uint32_t* sBits = (const uint32_t*)(sm + 49152);   // [128][64]
    const int tid = threadIdx.x;
    const int wid = tid >> 5, lane = tid & 31;
    const int mw = (wid >> 1) * 32;
    const int nw = (wid & 1) * 32;
    const int q0 = blockIdx.x * 128;
    const int bh = blockIdx.y;
    const int b  = bh >> 4;
    const int g = lane >> 2, tg = lane & 3;

    const __half* Kb = Kp + (size_t)bh * L_ * D_;
    const uint32_t* bb = mbits + ((size_t)b * L_ + q0) * (L_ / 32);
    __half* eb = eatt + (size_t)bh * L_ * L_;

    // prologue: Q + bits; K tiles 0,1,2 in flight (depth-4 ring)
    cpa_tile<128>(sb, Q + ((size_t)bh * L_ + q0) * D_, D_, tid);
#pragma unroll
    for (int t = 0; t < 8; t++) {
        int idx = tid + t * 256;
        cp16(sb + 49152 + idx * 16, bb + idx * 4);
    }
    cpa_tile<64>(sb + 16384, Kb, D_, tid);
    CP_COMMIT();
    cpa_tile<64>(sb + 16384 + 8192, Kb + (size_t)64 * D_, D_, tid);
    CP_COMMIT();
    cpa_tile<64>(sb + 16384 + 16384, Kb + (size_t)128 * D_, D_, tid);
    CP_COMMIT();

    float rs[MF][2];
#pragma unroll
    for (int i = 0; i < MF; i++) rs[i][0] = rs[i][1] = 0.0f;

    for (int kt = 0; kt < 32; kt++) {
        const uint32_t kb = sb + 16384 + (kt & 3) * 8192;
        if (kt < 30)       CP_WAIT(2);
        else if (kt == 30) CP_WAIT(1);
        else               CP_WAIT(0);
        __syncthreads();
        if (kt + 3 < 32) {   // issue-after-sync
            cpa_tile<64>(sb + 16384 + ((kt + 3) & 3) * 8192,
                         Kb + (size_t)(kt + 3) * 64 * D_, D_, tid);
            CP_COMMIT();
        }

        float acc[MF][NF][4];
#pragma unroll
        for (int i = 0; i < MF; i++)
#pragma unroll
            for (int j = 0; j < NF; j++)
#pragma unroll
                for (int kk = 0; kk < 4; kk++) acc[i][j][kk] = 0.0f;

        chunk_sn(acc, sb, kb, mw, nw, lane);

        const int k0 = kt * 64;
#pragma unroll
        for (int mf = 0; mf < MF; mf++) {
            const int r0 = mw + mf * 16 + g;
            const int r1 = r0 + 8;
#pragma unroll
            for (int nf = 0; nf < NF; nf++) {
                int knw = nw + nf * 8 + tg * 2;
                int wsel = kt * 2 + (knw >> 5);
                uint32_t w0 = sBits[r0 * 64 + wsel];
                uint32_t w1 = sBits[r1 * 64 + wsel];
                int bp = knw & 31;
                float2 e1, e2;
                e1.x = (w0 >> bp) & 1u       ? __expf(acc[mf][nf][0] * SCALE) : 0.0f;
                e1.y = (w0 >> (bp + 1)) & 1u ? __expf(acc[mf][nf][1] * SCALE) : 0.0f;
                e2.x = (w1 >> bp) & 1u       ? __expf(acc[mf][nf][2] * SCALE) : 0.0f;
                e2.y = (w1 >> (bp + 1)) & 1u ? __expf(acc[mf][nf][3] * SCALE) : 0.0f;
                rs[mf][0] += e1.x + e1.y;
                rs[mf][1] += e2.x + e2.y;
                *(__half2*)(eb + (size_t)(q0 + r0) * L_ + k0 + knw) =
                    __floats2half2_rn(e1.x, e1.y);
                *(__half2*)(eb + (size_t)(q0 + r1) * L_ + k0 + knw) =
                    __floats2half2_rn(e2.x, e2.y);
            }
        }
    }

#pragma unroll
    for (int mf = 0; mf < MF; mf++)
#pragma unroll
        for (int rr = 0; rr < 2; rr++) {
            float s = rs[mf][rr];
            s += __shfl_xor_sync(0xffffffffu, s, 1);
            s += __shfl_xor_sync(0xffffffffu, s, 2);
            if (tg == 0) sRed[mw + mf * 16 + g + rr * 8][wid & 1] = s;
        }
    __syncthreads();
    if (tid < 128)
        gl[(size_t)bh * L_ + q0 + tid] = sRed[tid][0] + sRed[tid][1];
}

// ---------------------------------------------------------------------------
// Kernel: AV (plain fp16, 1 product) + normalization. Single sync/chunk.
// smem (dynamic, 56KB): At 2x16K @0 | V 3x8K @32768
// ---------------------------------------------------------------------------
#define AV_SMEM (57344)

__global__ __launch_bounds__(256, 2)
void av_mma(const __half* __restrict__ eatt, float* __restrict__ att,
            const __half* __restrict__ V,
            const float* __restrict__ gl, __half* __restrict__ C)
{
    extern __shared__ char sm[];
    __shared__ float sI[128];
    const uint32_t sb = smem_u32(sm);
    const int tid = threadIdx.x;
    const int wid = tid >> 5, lane = tid & 31;
    const int mw = (wid >> 1) * 32;
    const int nw = (wid & 1) * 32;
    const int m0 = blockIdx.x * 128;
    const int bh = blockIdx.y;
    const int b  = bh >> 4, h = bh & 15;

    const __half* Eb = eatt + (size_t)bh * L_ * L_ + (size_t)m0 * L_;
    float*        Ao = att  + (size_t)bh * L_ * L_ + (size_t)m0 * L_;
    const __half* Vb = V + (size_t)bh * L_ * D_;

    if (tid < 128) sI[tid] = 1.0f / gl[(size_t)bh * L_ + m0 + tid];

    float acc[MF][NF][4];
#pragma unroll
    for (int i = 0; i < MF; i++)
#pragma unroll
        for (int j = 0; j < NF; j++)
#pragma unroll
            for (int kk = 0; kk < 4; kk++) acc[i][j][kk] = 0.0f;

    uint2 ea[8];
    // prologue: ea(0) regs; V(0), V(1) in flight
#pragma unroll
    for (int t = 0; t < 8; t++) {
        int idx = tid + t * 256;
        int r = idx >> 4, q = idx & 15;
        ea[t] = *(const uint2*)(Eb + (size_t)r * L_ + q * 4);
    }
    cpa_tile<64>(sb + 32768, Vb, D_, tid);
    CP_COMMIT();
    cpa_tile<64>(sb + 32768 + 8192, Vb + (size_t)64 * D_, D_, tid);
    CP_COMMIT();
    __syncthreads();    // sI visible

    // chunk 0 -> At[0] (+att write); prefetch ea(1)
#pragma unroll
    for (int t = 0; t < 8; t++) {
        int idx = tid + t * 256;
        int r = idx >> 4, q = idx & 15;
        float2 f01 = __half22float2(*(__half2*)&ea[t].x);
        float2 f23 = __half22float2(*(__half2*)&ea[t].y);
        float4 p;
        p.x = f01.x * sI[r]; p.y = f01.y * sI[r];
        p.z = f23.x * sI[r]; p.w = f23.y * sI[r];
        *(float4*)(Ao + (size_t)r * L_ + q * 4) = p;
        *(uint2*)(sm + swz(r, q * 8)) = ea[t];        // At[0]
    }
#pragma unroll
    for (int t = 0; t < 8; t++) {
        int idx = tid + t * 256;
        int r = idx >> 4, q = idx & 15;
        ea[t] = *(const uint2*)(Eb + (size_t)r * L_ + 64 + q * 4);
    }

    for (int c = 0; c < 32; c++) {
        if (c < 31) CP_WAIT(1);         // V(c) done (V(c+1) in flight)
        else        CP_WAIT(0);
        __syncthreads();                // At[c&1] visible; mma c-1 done
        if (c < 31) {
            // store ea (chunk c+1) -> At[(c+1)&1] + write normalized att
#pragma unroll
            for (int t = 0; t < 8; t++) {
                int idx = tid + t * 256;
                int r = idx >> 4, q = idx & 15;
                float2 f01 = __half22float2(*(__half2*)&ea[t].x);
                float2 f23 = __half22float2(*(__half2*)&ea[t].y);
                float4 p;
                p.x = f01.x * sI[r]; p.y = f01.y * sI[r];
                p.z = f23.x * sI[r]; p.w = f23.y * sI[r];
                *(float4*)(Ao + (size_t)r * L_ + (c + 1) * 64 + q * 4) = p;
                *(uint2*)(sm + ((c + 1) & 1) * 16384 + swz(r, q * 8)) = ea[t];
            }
            // prefetch ea(c+2) regs (rides under the mma)
            if (c < 30) {
#pragma unroll
                for (int t = 0; t < 8; t++) {
                    int idx = tid + t * 256;
                    int r = idx >> 4, q = idx & 15;
                    ea[t] = *(const uint2*)(Eb + (size_t)r * L_ + (c + 2) * 64 + q * 4);
                }
            }
            // issue V(c+2)
            if (c + 2 < 32) {
                cpa_tile<64>(sb + 32768 + ((c + 2) % 3) * 8192,
                             Vb + (size_t)(c + 2) * 64 * D_, D_, tid);
                CP_COMMIT();
            }
        }
        chunk_pt(acc, sb + (c & 1) * 16384, sb + 32768 + (c % 3) * 8192,
                 mw, nw, lane);
    }

    // epilogue: scale unnormalized ctx rows by inv_l, write plain fp16
    const int g = lane >> 2, tg = lane & 3;
#pragma unroll
    for (int mf = 0; mf < MF; mf++)
#pragma unroll
        for (int nf = 0; nf < NF; nf++) {
            int r0l = mw + mf * 16 + g;
            int r1l = r0l + 8;
            float s0 = sI[r0l], s1 = sI[r1l];
            int m   = m0 + r0l;
            int col = nw + nf * 8 + tg * 2;
            size_t i0 = ((size_t)b * L_ + m) * E_ + h * D_ + col;
            size_t i1 = i0 + 8 * E_;
            *(uint32_t*)&C[i0] = pack_hf2(__float2half(acc[mf][nf][0] * s0),
                                          __float2half(acc[mf][nf][1] * s0));
            *(uint32_t*)&C[i1] = pack_hf2(__float2half(acc[mf][nf][2] * s1),
                                          __float2half(acc[mf][nf][3] * s1));
        }
}

// ---------------------------------------------------------------------------
// Launch (single stream)
// ---------------------------------------------------------------------------
extern "C" void kernel_launch(void* const* d_in, const int* in_sizes, int n_in,
                              void* d_out, int out_size)
{
    const float* iq = (const float*)d_in[0];
    const float* ik = (const float*)d_in[1];
    const float* iv = (const float*)d_in[2];
    const int*   mk = (const int*)  d_in[3];
    const float* Wq = (const float*)d_in[4];
    const float* bq = (const float*)d_in[5];
    const float* Wk = (const float*)d_in[6];
    const float* bk = (const float*)d_in[7];
    const float* Wv = (const float*)d_in[8];
    const float* bv = (const float*)d_in[9];
    const float* Wo = (const float*)d_in[10];
    const float* bo = (const float*)d_in[11];

    float* o_out = (float*)d_out;
    const long long o_elems   = (long long)MTOK * E_;
    const long long att_elems = (long long)B_ * H_ * L_ * L_;

    __half *Qp, *Kp, *Vp, *Ea, *Cc, *Xq, *Xk, *Xv;
    __half *dWq, *dWk, *dWv, *dWo;
    uint32_t* Mb;
    float *Slv, *Ap;
    cudaGetSymbolAddress((void**)&Qp, g_Q);
    cudaGetSymbolAddress((void**)&Kp, g_K);
    cudaGetSymbolAddress((void**)&Vp, g_V);
    cudaGetSymbolAddress((void**)&Xq, g_Xq);
    cudaGetSymbolAddress((void**)&Xk, g_Xk);
    cudaGetSymbolAddress((void**)&Xv, g_Xv);
    cudaGetSymbolAddress((void**)&dWq, g_Wq);
    cudaGetSymbolAddress((void**)&dWk, g_Wk);
    cudaGetSymbolAddress((void**)&dWv, g_Wv);
    cudaGetSymbolAddress((void**)&dWo, g_Wo);
    cudaGetSymbolAddress((void**)&Cc, g_C);
    cudaGetSymbolAddress((void**)&Mb, g_mbits);
    cudaGetSymbolAddress((void**)&Slv, g_sl);
    cudaGetSymbolAddress((void**)&Ea, g_eatt);
    cudaGetSymbolAddress((void**)&Ap, g_att_fallback);

    float* att = ((long long)out_size >= o_elems + att_elems)
                     ? (o_out + o_elems) : Ap;

    cudaFuncSetAttribute(proj_qkv,   cudaFuncAttributeMaxDynamicSharedMemorySize, PROJ_SMEM);
    cudaFuncSetAttribute(proj_o,     cudaFuncAttributeMaxDynamicSharedMemorySize, PROJ_SMEM);
    cudaFuncSetAttribute(scores_mma, cudaFuncAttributeMaxDynamicSharedMemorySize, SCORES_SMEM);
    cudaFuncSetAttribute(av_mma,     cudaFuncAttributeMaxDynamicSharedMemorySize, AV_SMEM);

    // fused prologue
    prep_all<<<45056, 256>>>(iq, ik, iv, mk, Wq, Wk, Wv, Wo,
                             Xq, Xk, Xv, dWq, dWk, dWv, dWo, Mb);

    // fused QKV projection (plain fp16)
    dim3 gp(E_ / 64, MTOK / 128, 3);            // (16, 64, 3)
    proj_qkv<<<gp, 256, PROJ_SMEM>>>(Xq, Xk, Xv, dWq, dWk, dWv,
                                     bq, bk, bv, Qp, Kp, Vp);

    // scores (plain fp16, depth-4 K pipeline)
    dim3 gs(L_ / 128, B_ * H_);                 // (16, 64)
    scores_mma<<<gs, 256, SCORES_SMEM>>>(Qp, Kp, Mb, Ea, Slv);

    // AV (plain fp16, single-sync pipeline)
    av_mma<<<gs, 256, AV_SMEM>>>(Ea, att, Vp, Slv, Cc);

    // output projection
    dim3 go(E_ / 64, MTOK / 128);               // (16, 64)
    proj_o<<<go, 256, PROJ_SMEM>>>(Cc, dWo, bo, o_out);
}